// round 16
// baseline (speedup 1.0000x reference)
#include <cuda_runtime.h>
#include <cuda_fp16.h>
#include <math.h>
#include <cstdint>

#define BB 4
#define NN 8192
#define NSL 8

// ---------------- device scratch ----------------
__device__ float g_tproj[BB*256];
__device__ float g_pbest[NSL*BB*NN];
__device__ int   g_pidx [NSL*BB*NN];
// fragment-contiguous fp16 weight planes:
// per layer: [ngrp(32)][kc(8)][plane(2)][128 u32]; block of 128 u32 = warp fragment,
// lane (g,tt) owns u32s (g*4+tt)*4 .. +3.  hi = f16(W); lo = f16((W-hi)*2048)
__device__ uint32_t g_w1[4*65536];
__device__ uint32_t g_w2[4*65536];
__device__ uint32_t g_ow[32768];

// ================= helpers =================
__device__ __forceinline__ uint32_t smem_to_u32(const void* p) {
    uint32_t a;
    asm("{ .reg .u64 t; cvta.to.shared.u64 t, %1; cvt.u32.u64 %0, t; }" : "=r"(a) : "l"(p));
    return a;
}
#define LD4(r0,r1,r2,r3,ba) asm volatile("ld.shared.v4.u32 {%0,%1,%2,%3}, [%4];" \
    : "=r"(r0),"=r"(r1),"=r"(r2),"=r"(r3) : "r"(ba))
#define ST4(ba,r0,r1,r2,r3) asm volatile("st.shared.v4.b32 [%0], {%1,%2,%3,%4};" \
    :: "r"(ba),"r"(r0),"r"(r1),"r"(r2),"r"(r3) : "memory")

__device__ __forceinline__ uint32_t packh2(float x0, float x1) {
    uint32_t u;
    asm("cvt.rn.f16x2.f32 %0, %1, %2;" : "=r"(u) : "f"(x1), "f"(x0));
    return u;
}
__device__ __forceinline__ void splitx2(float x0, float x1, uint32_t& hi, uint32_t& lo) {
    hi = packh2(x0, x1);
    __half2 hh = *reinterpret_cast<__half2*>(&hi);
    float h0 = __low2float(hh), h1 = __high2float(hh);
    lo = packh2((x0 - h0)*2048.f, (x1 - h1)*2048.f);
}
__device__ __forceinline__ void mmaf16(float c[4], const uint32_t a[4], const uint32_t b[2]) {
    asm volatile(
        "mma.sync.aligned.m16n8k16.row.col.f32.f16.f16.f32 "
        "{%0,%1,%2,%3}, {%4,%5,%6,%7}, {%8,%9}, {%0,%1,%2,%3};"
        : "+f"(c[0]), "+f"(c[1]), "+f"(c[2]), "+f"(c[3])
        : "r"(a[0]), "r"(a[1]), "r"(a[2]), "r"(a[3]), "r"(b[0]), "r"(b[1]));
}
__device__ __forceinline__ float silu(float x) { return x / (1.0f + __expf(-x)); }
#define INV2048 4.8828125e-4f

// mlp smem u32 offsets; planes: 32 rows x 144 u32 (stride 576B = 64 mod 128, LDS.128 conflict-free)
#define O_XH    0        // 4608  residual hi (f16x2)
#define O_XL    4608     // 4608  residual lo (f16x2, x2048)
#define O_HH    9216     // 4608  h plane; reused as fp32 y1 [32][132]
#define O_SRS   13824    // 32 x 8 f
#define O_SRQ   14080
#define O_MU    14336
#define O_RS    14368
#define O_FEAT  14400    // 32 x 6 f
#define SMEM_U32 14592
#define SMEM_BYTES (SMEM_U32*4)

// =====================================================================
// prep_kernel: fuses nn / splitw / temb (independent) into one launch.
// blocks [0,256): nn — 8 slices of 1024 targets; 256 thr, 4 points/thread
// blocks [256,832): splitw
// blocks [832,836): temb
// =====================================================================
#define SLTS 1024
#define PREP_NN    256
#define PREP_SPW   832
#define PREP_TOTAL 836

__global__ __launch_bounds__(256)
void prep_kernel(const float* __restrict__ noisy, const float* __restrict__ target,
                 const int* __restrict__ timesteps,
                 const float* __restrict__ te_w1, const float* __restrict__ te_b1,
                 const float* __restrict__ te_w2, const float* __restrict__ te_b2,
                 const float* __restrict__ tp_w,  const float* __restrict__ tp_b,
                 const float* __restrict__ ly_w1, const float* __restrict__ ly_w2,
                 const float* __restrict__ out_w1)
{
    __shared__ float4 shm4[SLTS];     // 16 KB, aliased by all roles
    int t = threadIdx.x;
    int blk = blockIdx.x;

    if (blk < PREP_NN) {
        // ---------------- nn role: Q=4 points/thread over 1024-target slice ----------------
        int b = blk >> 6, pg = (blk >> 3) & 7, slice = blk & 7;
        const float4* tg4 = (const float4*)(target + ((size_t)b*NN + (size_t)slice*SLTS) * 3);
        {
            float4 v0 = tg4[3*t], v1 = tg4[3*t+1], v2 = tg4[3*t+2];
            shm4[4*t+0] = make_float4(v0.x, v0.y, v0.z, 0.5f*(v0.x*v0.x + v0.y*v0.y + v0.z*v0.z));
            shm4[4*t+1] = make_float4(v0.w, v1.x, v1.y, 0.5f*(v0.w*v0.w + v1.x*v1.x + v1.y*v1.y));
            shm4[4*t+2] = make_float4(v1.z, v1.w, v2.x, 0.5f*(v1.z*v1.z + v1.w*v1.w + v2.x*v2.x));
            shm4[4*t+3] = make_float4(v2.y, v2.z, v2.w, 0.5f*(v2.y*v2.y + v2.z*v2.z + v2.w*v2.w));
        }
        __syncthreads();
        float qx[4], qy[4], qz[4], best[4];
        int bidx[4];
        int p0 = pg*1024 + t;
        #pragma unroll
        for (int i = 0; i < 4; i++) {
            const float* q = noisy + ((size_t)b*NN + p0 + 256*i) * 3;
            qx[i] = -q[0]; qy[i] = -q[1]; qz[i] = -q[2];
            best[i] = INFINITY; bidx[i] = 0;
        }
        #pragma unroll 2
        for (int j = 0; j < SLTS; j++) {
            float4 v = shm4[j];
            #pragma unroll
            for (int i = 0; i < 4; i++) {
                float e = fmaf(qx[i], v.x, v.w);
                e = fmaf(qy[i], v.y, e);
                e = fmaf(qz[i], v.z, e);
                if (e < best[i]) { best[i] = e; bidx[i] = j; }
            }
        }
        #pragma unroll
        for (int i = 0; i < 4; i++) {
            int pi = b*NN + p0 + 256*i;
            g_pbest[slice*(BB*NN) + pi] = best[i];
            g_pidx [slice*(BB*NN) + pi] = slice*SLTS + bidx[i];
        }
    } else if (blk < PREP_SPW) {
        // ---------------- splitw role: fragment-contiguous repack ----------------
        float (*ts)[33] = reinterpret_cast<float(*)[33]>(shm4);
        int sb = blk - PREP_NN;
        int m = sb >> 6, tile = sb & 63;
        const float* src; uint32_t* dst; int N = 256;
        if (m < 4)      { src = ly_w1 + m*65536;     dst = g_w1 + m*65536; }
        else if (m < 8) { src = ly_w2 + (m-4)*65536; dst = g_w2 + (m-4)*65536; }
        else            { src = out_w1;              dst = g_ow; N = 128; }
        int tn = (tile & 7) * 32, tk = (tile >> 3) * 32;   // tk multiple of 32
        if (tn >= N) return;
        int lx = t & 31, ly = t >> 5;
        #pragma unroll
        for (int i = 0; i < 32; i += 8) ts[ly+i][lx] = src[(tk+ly+i)*N + tn + lx];
        __syncthreads();
        int kk = lx & 15; bool ishi = lx < 16;
        int pos = ((kk & 3) << 2) | (kk >> 2);   // M-perm: transpose within 16
        int kc = tk >> 5;
        int plane = ishi ? 0 : 128;
        #pragma unroll
        for (int i = 0; i < 32; i += 8) {
            int nl = ly + i;
            float x0 = ts[2*kk][nl], x1 = ts[2*kk+1][nl];
            __half2 hh = __floats2half2_rn(x0, x1);
            float h0 = __low2float(hh), h1 = __high2float(hh);
            __half2 llv = __floats2half2_rn((x0 - h0)*2048.f, (x1 - h1)*2048.f);
            int n = tn + nl;
            int idx = (n >> 3)*2048 + kc*256 + plane + (n & 7)*16 + pos;
            dst[idx] = ishi ? *reinterpret_cast<uint32_t*>(&hh)
                            : *reinterpret_cast<uint32_t*>(&llv);
        }
    } else {
        // ---------------- temb role (256 threads) ----------------
        float* sp  = (float*)shm4;
        float* emb = sp;           // 128
        float* h1  = sp + 128;     // 512
        float* h2  = sp + 640;     // 512
        int b = blk - PREP_SPW;
        if (t < 64) {
            float fr = expf((float)t * (-logf(10000.0f) / 63.0f));
            float an = (float)timesteps[b] * fr;
            emb[t] = sinf(an); emb[t+64] = cosf(an);
        }
        __syncthreads();
        #pragma unroll
        for (int j = t; j < 512; j += 256) {
            float a = te_b1[j];
            #pragma unroll 4
            for (int k = 0; k < 128; k++) a = fmaf(emb[k], te_w1[k*512+j], a);
            h1[j] = a / (1.0f + expf(-a));
        }
        __syncthreads();
        #pragma unroll
        for (int j = t; j < 512; j += 256) {
            float a = te_b2[j];
            #pragma unroll 4
            for (int k = 0; k < 512; k++) a = fmaf(h1[k], te_w2[k*512+j], a);
            h2[j] = a;
        }
        __syncthreads();
        {
            float a = tp_b[t];
            #pragma unroll 4
            for (int k = 0; k < 512; k++) a = fmaf(h2[k], tp_w[k*256+t], a);
            g_tproj[b*256+t] = a;
        }
    }
}

// ============ fused fp16 weight-pair MLP, B direct from gmem (fragment-contiguous) ============
template<int NT>
__device__ __forceinline__ void gemm_ldg(uint32_t su, int Ao,
                                         const uint32_t* __restrict__ gw,
                                         float ch[2][NT][4], float cl[2][NT][4],
                                         int wn, int g, int tt)
{
    const uint32_t* pb[NT];
    #pragma unroll
    for (int nt = 0; nt < NT; nt++)
        pb[nt] = gw + (wn*NT + nt)*2048 + (g*4 + tt)*4;
    #pragma unroll
    for (int kc = 0; kc < 8; kc++) {
        uint4 bhv[NT], blv[NT];
        #pragma unroll
        for (int nt = 0; nt < NT; nt++) {
            bhv[nt] = *(const uint4*)(pb[nt] + kc*256);
            blv[nt] = *(const uint4*)(pb[nt] + kc*256 + 128);
        }
        uint32_t af[2][2][4];
        #pragma unroll
        for (int mi = 0; mi < 2; mi++) {
            uint32_t ad = su + (uint32_t)((Ao + (mi*16 + g)*144 + kc*16 + tt*4)*4);
            uint32_t q0,q1,q2,q3,p0,p1,p2,p3;
            LD4(q0,q1,q2,q3, ad);
            LD4(p0,p1,p2,p3, ad + 8*144*4);
            af[0][mi][0]=q0; af[0][mi][2]=q1; af[1][mi][0]=q2; af[1][mi][2]=q3;
            af[0][mi][1]=p0; af[0][mi][3]=p1; af[1][mi][1]=p2; af[1][mi][3]=p3;
        }
        #pragma unroll
        for (int ks = 0; ks < 2; ks++)
            #pragma unroll
            for (int mi = 0; mi < 2; mi++)
                #pragma unroll
                for (int nt = 0; nt < NT; nt++) {
                    uint32_t bh[2] = { ks ? bhv[nt].z : bhv[nt].x, ks ? bhv[nt].w : bhv[nt].y };
                    uint32_t bl[2] = { ks ? blv[nt].z : blv[nt].x, ks ? blv[nt].w : blv[nt].y };
                    mmaf16(ch[mi][nt], af[ks][mi], bh);
                    mmaf16(cl[mi][nt], af[ks][mi], bl);
                }
    }
}

__global__ __launch_bounds__(256, 2)
void mlp_f16(const float* __restrict__ noisy, const float* __restrict__ target,
             const float* __restrict__ in_w,  const float* __restrict__ in_b,
             const float* __restrict__ ly_b1, const float* __restrict__ ly_g,
             const float* __restrict__ ly_be, const float* __restrict__ ly_b2,
             const float* __restrict__ out_b1, const float* __restrict__ out_w2,
             const float* __restrict__ out_b2, float* __restrict__ out)
{
    extern __shared__ float sm[];
    uint32_t su = smem_to_u32(sm);
    int t = threadIdx.x, lane = t & 31;
    int wn = t >> 5;                       // warp grid 1(M) x 8(N)
    int g = lane >> 2, tt = lane & 3;
    int b = blockIdx.x >> 8, row0 = (blockIdx.x & 255) << 5;

    float* feat = sm + O_FEAT;

    if (t < 32) {   // fused nn_reduce over 8 slices (ascending => first-min)
        int pi = b*NN + row0 + t;
        float best = g_pbest[pi]; int bi = g_pidx[pi];
        #pragma unroll
        for (int s = 1; s < NSL; s++) {
            float vv = g_pbest[s*(BB*NN) + pi];
            if (vv < best) { best = vv; bi = g_pidx[s*(BB*NN) + pi]; }
        }
        const float* tc = target + ((size_t)b*NN + bi)*3;
        feat[t*6+0] = noisy[(size_t)pi*3+0]; feat[t*6+1] = noisy[(size_t)pi*3+1]; feat[t*6+2] = noisy[(size_t)pi*3+2];
        feat[t*6+3] = tc[0]; feat[t*6+4] = tc[1]; feat[t*6+5] = tc[2];
    }
    __syncthreads();

    // ---- input build in fragment layout -> XH/XL residual planes ----
    {
        const float* tp = g_tproj + b*256;
        float fr[2][2][6];
        #pragma unroll
        for (int mi = 0; mi < 2; mi++)
            #pragma unroll
            for (int h = 0; h < 2; h++) {
                int row = mi*16 + h*8 + g;
                #pragma unroll
                for (int k = 0; k < 6; k++) fr[mi][h][k] = feat[row*6 + k];
            }
        uint32_t wh[2][2][4], wl[2][2][4];
        #pragma unroll
        for (int nt = 0; nt < 4; nt++) {
            int bc = wn*32 + nt*8 + 2*tt;
            float xv[2][2][2];
            #pragma unroll
            for (int half = 0; half < 2; half++) {
                int col = bc + half;
                float base = in_b[col] + tp[col];
                float w[6];
                #pragma unroll
                for (int k = 0; k < 6; k++) w[k] = in_w[k*256 + col];
                #pragma unroll
                for (int mi = 0; mi < 2; mi++)
                    #pragma unroll
                    for (int h = 0; h < 2; h++) {
                        float a = base;
                        #pragma unroll
                        for (int k = 0; k < 6; k++) a = fmaf(fr[mi][h][k], w[k], a);
                        xv[mi][h][half] = a;
                    }
            }
            #pragma unroll
            for (int mi = 0; mi < 2; mi++)
                #pragma unroll
                for (int h = 0; h < 2; h++)
                    splitx2(xv[mi][h][0], xv[mi][h][1], wh[mi][h][nt], wl[mi][h][nt]);
        }
        #pragma unroll
        for (int mi = 0; mi < 2; mi++)
            #pragma unroll
            for (int h = 0; h < 2; h++) {
                int row = mi*16 + h*8 + g;
                uint32_t off = (uint32_t)((row*144 + wn*16 + tt*4)*4);
                ST4(su + (uint32_t)(O_XH*4) + off, wh[mi][h][0], wh[mi][h][1], wh[mi][h][2], wh[mi][h][3]);
                ST4(su + (uint32_t)(O_XL*4) + off, wl[mi][h][0], wl[mi][h][1], wl[mi][h][2], wl[mi][h][3]);
            }
    }
    __syncthreads();   // publish XH/XL

    // ---- 4 residual layers ----
    #pragma unroll 1
    for (int lay = 0; lay < 4; lay++) {
        const float* b1p = ly_b1 + lay*256;
        const float* gap = ly_g  + lay*256;
        const float* bep = ly_be + lay*256;
        const float* b2p = ly_b2 + lay*256;

        // GEMM1: D = x @ W1 (no barriers inside)
        float ch[2][4][4], cl[2][4][4];
        #pragma unroll
        for (int mi = 0; mi < 2; mi++)
            #pragma unroll
            for (int nt = 0; nt < 4; nt++)
                #pragma unroll
                for (int e = 0; e < 4; e++) { ch[mi][nt][e] = 0.f; cl[mi][nt][e] = 0.f; }
        gemm_ldg<4>(su, O_XH, g_w1 + lay*65536, ch, cl, wn, g, tt);

        // epilogue1: combine into ch, LN stats
        float S[2][2] = {{0,0},{0,0}}, Q[2][2] = {{0,0},{0,0}};
        #pragma unroll
        for (int mi = 0; mi < 2; mi++)
            #pragma unroll
            for (int nt = 0; nt < 4; nt++) {
                int bc = wn*32 + nt*8 + 2*tt;
                float b0 = b1p[bc], b1v = b1p[bc + 1];
                float v0 = fmaf(cl[mi][nt][0], INV2048, ch[mi][nt][0]) + b0;
                float v1 = fmaf(cl[mi][nt][1], INV2048, ch[mi][nt][1]) + b1v;
                float v2 = fmaf(cl[mi][nt][2], INV2048, ch[mi][nt][2]) + b0;
                float v3 = fmaf(cl[mi][nt][3], INV2048, ch[mi][nt][3]) + b1v;
                ch[mi][nt][0]=v0; ch[mi][nt][1]=v1; ch[mi][nt][2]=v2; ch[mi][nt][3]=v3;
                S[mi][0] += v0 + v1; Q[mi][0] = fmaf(v0,v0,fmaf(v1,v1,Q[mi][0]));
                S[mi][1] += v2 + v3; Q[mi][1] = fmaf(v2,v2,fmaf(v3,v3,Q[mi][1]));
            }
        #pragma unroll
        for (int mi = 0; mi < 2; mi++)
            #pragma unroll
            for (int h = 0; h < 2; h++) {
                float s = S[mi][h], q = Q[mi][h];
                s += __shfl_xor_sync(~0u, s, 1); s += __shfl_xor_sync(~0u, s, 2);
                q += __shfl_xor_sync(~0u, q, 1); q += __shfl_xor_sync(~0u, q, 2);
                if (tt == 0) {
                    int row = mi*16 + h*8 + g;
                    sm[O_SRS + row*8 + wn] = s;
                    sm[O_SRQ + row*8 + wn] = q;
                }
            }
        __syncthreads();
        if (t < 32) {
            float s = 0.f, q = 0.f;
            #pragma unroll
            for (int i = 0; i < 8; i++) { s += sm[O_SRS + t*8 + i]; q += sm[O_SRQ + t*8 + i]; }
            float mu = s * (1.f/256.f);
            sm[O_RS + t] = rsqrtf(fmaf(-mu, mu, q * (1.f/256.f)) + 1e-5f);
            sm[O_MU + t] = mu;
        }
        __syncthreads();
        // LN + SiLU -> h plane
        #pragma unroll
        for (int mi = 0; mi < 2; mi++)
            #pragma unroll
            for (int h = 0; h < 2; h++) {
                int row = mi*16 + h*8 + g;
                float mu = sm[O_MU + row], rs = sm[O_RS + row];
                uint32_t w4[4];
                #pragma unroll
                for (int nt = 0; nt < 4; nt++) {
                    int bc = wn*32 + nt*8 + 2*tt;
                    float h0 = silu(fmaf((ch[mi][nt][2*h]   - mu)*rs, gap[bc],   bep[bc]));
                    float h1 = silu(fmaf((ch[mi][nt][2*h+1] - mu)*rs, gap[bc+1], bep[bc+1]));
                    w4[nt] = packh2(h0, h1);
                }
                ST4(su + (uint32_t)((O_HH + row*144 + wn*16 + tt*4)*4), w4[0], w4[1], w4[2], w4[3]);
            }
        __syncthreads();   // publish h plane

        // GEMM2: D = h @ W2
        #pragma unroll
        for (int mi = 0; mi < 2; mi++)
            #pragma unroll
            for (int nt = 0; nt < 4; nt++)
                #pragma unroll
                for (int e = 0; e < 4; e++) { ch[mi][nt][e] = 0.f; cl[mi][nt][e] = 0.f; }
        gemm_ldg<4>(su, O_HH, g_w2 + lay*65536, ch, cl, wn, g, tt);

        // epilogue2: x = x_old(XH/XL planes) + D + b2; refresh planes
        #pragma unroll
        for (int mi = 0; mi < 2; mi++)
            #pragma unroll
            for (int h = 0; h < 2; h++) {
                int row = mi*16 + h*8 + g;
                uint32_t off = (uint32_t)((row*144 + wn*16 + tt*4)*4);
                uint32_t oh0,oh1,oh2,oh3, ol0,ol1,ol2,ol3;
                LD4(oh0,oh1,oh2,oh3, su + (uint32_t)(O_XH*4) + off);
                LD4(ol0,ol1,ol2,ol3, su + (uint32_t)(O_XL*4) + off);
                uint32_t ohs[4] = {oh0,oh1,oh2,oh3};
                uint32_t ols[4] = {ol0,ol1,ol2,ol3};
                uint32_t nh[4], nl[4];
                #pragma unroll
                for (int nt = 0; nt < 4; nt++) {
                    int bc = wn*32 + nt*8 + 2*tt;
                    float2 xo = __half22float2(*reinterpret_cast<__half2*>(&ohs[nt]));
                    float2 xl = __half22float2(*reinterpret_cast<__half2*>(&ols[nt]));
                    float x0 = fmaf(xl.x, INV2048, xo.x) + fmaf(cl[mi][nt][2*h],   INV2048, ch[mi][nt][2*h])   + b2p[bc];
                    float x1 = fmaf(xl.y, INV2048, xo.y) + fmaf(cl[mi][nt][2*h+1], INV2048, ch[mi][nt][2*h+1]) + b2p[bc + 1];
                    splitx2(x0, x1, nh[nt], nl[nt]);
                }
                ST4(su + (uint32_t)(O_XH*4) + off, nh[0], nh[1], nh[2], nh[3]);
                ST4(su + (uint32_t)(O_XL*4) + off, nl[0], nl[1], nl[2], nl[3]);
            }
        __syncthreads();   // publish refreshed x planes
    }

    // ---- head GEMM: D = x @ out_w1 (N=128) ----
    {
        float ch[2][2][4], cl[2][2][4];
        #pragma unroll
        for (int mi = 0; mi < 2; mi++)
            #pragma unroll
            for (int nt = 0; nt < 2; nt++)
                #pragma unroll
                for (int e = 0; e < 4; e++) { ch[mi][nt][e] = 0.f; cl[mi][nt][e] = 0.f; }
        gemm_ldg<2>(su, O_XH, g_ow, ch, cl, wn, g, tt);

        __syncthreads();   // XH reads done before HH region reused as fp32 y1
        float* y1f = sm + O_HH;
        #pragma unroll
        for (int mi = 0; mi < 2; mi++)
            #pragma unroll
            for (int h = 0; h < 2; h++) {
                int row = mi*16 + h*8 + g;
                #pragma unroll
                for (int nt = 0; nt < 2; nt++) {
                    int bc = wn*16 + nt*8 + 2*tt;
                    float v0 = fmaf(cl[mi][nt][2*h],   INV2048, ch[mi][nt][2*h])   + out_b1[bc];
                    float v1 = fmaf(cl[mi][nt][2*h+1], INV2048, ch[mi][nt][2*h+1]) + out_b1[bc+1];
                    y1f[row*132 + bc]     = silu(v0);
                    y1f[row*132 + bc + 1] = silu(v1);
                }
            }
    }
    __syncthreads();

    // ---- final: score = y1 @ out_w2 + out_b2 (128 -> 3, fp32) ----
    if (t < 96) {
        int rr = t / 3, p = t - rr*3;
        float a = out_b2[p];
        const float* y = sm + O_HH + rr*132;
        #pragma unroll 8
        for (int k = 0; k < 128; k++) a = fmaf(y[k], out_w2[k*3 + p], a);
        out[(size_t)((b*NN + row0 + rr)*3 + p)] = a;
    }
}

// =====================================================================
extern "C" void kernel_launch(void* const* d_in, const int* in_sizes, int n_in,
                              void* d_out, int out_size)
{
    const float* noisy  = (const float*)d_in[0];
    const float* target = (const float*)d_in[1];
    const int*   tsteps = (const int*)  d_in[2];
    const float* te_w1  = (const float*)d_in[3];
    const float* te_b1  = (const float*)d_in[4];
    const float* te_w2  = (const float*)d_in[5];
    const float* te_b2  = (const float*)d_in[6];
    const float* tp_w   = (const float*)d_in[7];
    const float* tp_b   = (const float*)d_in[8];
    const float* in_w   = (const float*)d_in[9];
    const float* in_b   = (const float*)d_in[10];
    const float* ly_w1  = (const float*)d_in[11];
    const float* ly_b1  = (const float*)d_in[12];
    const float* ly_g   = (const float*)d_in[13];
    const float* ly_be  = (const float*)d_in[14];
    const float* ly_w2  = (const float*)d_in[15];
    const float* ly_b2  = (const float*)d_in[16];
    const float* out_w1 = (const float*)d_in[17];
    const float* out_b1 = (const float*)d_in[18];
    const float* out_w2 = (const float*)d_in[19];
    const float* out_b2 = (const float*)d_in[20];
    float* out = (float*)d_out;

    cudaFuncSetAttribute(mlp_f16, cudaFuncAttributeMaxDynamicSharedMemorySize, SMEM_BYTES);

    prep_kernel<<<PREP_TOTAL, 256>>>(noisy, target, tsteps,
                                     te_w1, te_b1, te_w2, te_b2, tp_w, tp_b,
                                     ly_w1, ly_w2, out_w1);
    mlp_f16<<<1024, 256, SMEM_BYTES>>>(noisy, target, in_w, in_b,
                                       ly_b1, ly_g, ly_be, ly_b2,
                                       out_b1, out_w2, out_b2, out);
}

// round 17
// speedup vs baseline: 1.0452x; 1.0452x over previous
#include <cuda_runtime.h>
#include <cuda_fp16.h>
#include <math.h>
#include <cstdint>

#define BB 4
#define NN 8192
#define NSL 8

// ---------------- device scratch ----------------
__device__ float g_tproj[BB*256];
__device__ float g_pbest[NSL*BB*NN];
__device__ int   g_pidx [NSL*BB*NN];
// fp16 weight planes: [N][128] u32 (2 f16/u32 along K), k-pairs M-permuted within 16-groups
// hi = f16(W);  lo = f16((W - hi)*2048)
// NOTE (R16 lesson): this row-scattered layout makes each B-LDG touch 8 distinct
// 128B lines -> 8 parallel L2 requests; do NOT "coalesce" it (kills MLP, latency-bound).
__device__ uint32_t g_w1h[4*256*128], g_w1l[4*256*128];
__device__ uint32_t g_w2h[4*256*128], g_w2l[4*256*128];
__device__ uint32_t g_owh[128*128],   g_owl[128*128];

// ================= helpers =================
__device__ __forceinline__ uint32_t smem_to_u32(const void* p) {
    uint32_t a;
    asm("{ .reg .u64 t; cvta.to.shared.u64 t, %1; cvt.u32.u64 %0, t; }" : "=r"(a) : "l"(p));
    return a;
}
#define LD4(r0,r1,r2,r3,ba) asm volatile("ld.shared.v4.u32 {%0,%1,%2,%3}, [%4];" \
    : "=r"(r0),"=r"(r1),"=r"(r2),"=r"(r3) : "r"(ba))
#define ST4(ba,r0,r1,r2,r3) asm volatile("st.shared.v4.b32 [%0], {%1,%2,%3,%4};" \
    :: "r"(ba),"r"(r0),"r"(r1),"r"(r2),"r"(r3) : "memory")

__device__ __forceinline__ uint32_t packh2(float x0, float x1) {
    uint32_t u;
    asm("cvt.rn.f16x2.f32 %0, %1, %2;" : "=r"(u) : "f"(x1), "f"(x0));
    return u;
}
__device__ __forceinline__ void splitx2(float x0, float x1, uint32_t& hi, uint32_t& lo) {
    hi = packh2(x0, x1);
    __half2 hh = *reinterpret_cast<__half2*>(&hi);
    float h0 = __low2float(hh), h1 = __high2float(hh);
    lo = packh2((x0 - h0)*2048.f, (x1 - h1)*2048.f);
}
__device__ __forceinline__ void mmaf16(float c[4], const uint32_t a[4], const uint32_t b[2]) {
    asm volatile(
        "mma.sync.aligned.m16n8k16.row.col.f32.f16.f16.f32 "
        "{%0,%1,%2,%3}, {%4,%5,%6,%7}, {%8,%9}, {%0,%1,%2,%3};"
        : "+f"(c[0]), "+f"(c[1]), "+f"(c[2]), "+f"(c[3])
        : "r"(a[0]), "r"(a[1]), "r"(a[2]), "r"(a[3]), "r"(b[0]), "r"(b[1]));
}
__device__ __forceinline__ float silu(float x) { return x / (1.0f + __expf(-x)); }
#define INV2048 4.8828125e-4f

// mlp smem u32 offsets; planes: 32 rows x 144 u32 (stride 576B = 64 mod 128, LDS.128 conflict-free)
#define O_XH    0        // 4608  residual hi (f16x2)
#define O_XL    4608     // 4608  residual lo (f16x2, x2048)
#define O_HH    9216     // 4608  h plane; reused as fp32 y1 [32][132]
#define O_SRS   13824    // 32 x 8 f
#define O_SRQ   14080
#define O_MU    14336
#define O_RS    14368
#define O_FEAT  14400    // 32 x 6 f
#define SMEM_U32 14592
#define SMEM_BYTES (SMEM_U32*4)

// =====================================================================
// prep_kernel: fuses nn / splitw / temb (independent) into one launch.
// blocks [0,256): nn — 8 slices of 1024 targets; 256 thr, 4 points/thread
// blocks [256,832): splitw
// blocks [832,836): temb
// =====================================================================
#define SLTS 1024
#define PREP_NN    256
#define PREP_SPW   832
#define PREP_TOTAL 836

__global__ __launch_bounds__(256)
void prep_kernel(const float* __restrict__ noisy, const float* __restrict__ target,
                 const int* __restrict__ timesteps,
                 const float* __restrict__ te_w1, const float* __restrict__ te_b1,
                 const float* __restrict__ te_w2, const float* __restrict__ te_b2,
                 const float* __restrict__ tp_w,  const float* __restrict__ tp_b,
                 const float* __restrict__ ly_w1, const float* __restrict__ ly_w2,
                 const float* __restrict__ out_w1)
{
    __shared__ float4 shm4[SLTS];     // 16 KB, aliased by all roles
    int t = threadIdx.x;
    int blk = blockIdx.x;

    if (blk < PREP_NN) {
        // ---------------- nn role: Q=4 points/thread over 1024-target slice ----------------
        int b = blk >> 6, pg = (blk >> 3) & 7, slice = blk & 7;
        const float4* tg4 = (const float4*)(target + ((size_t)b*NN + (size_t)slice*SLTS) * 3);
        {
            float4 v0 = tg4[3*t], v1 = tg4[3*t+1], v2 = tg4[3*t+2];
            shm4[4*t+0] = make_float4(v0.x, v0.y, v0.z, 0.5f*(v0.x*v0.x + v0.y*v0.y + v0.z*v0.z));
            shm4[4*t+1] = make_float4(v0.w, v1.x, v1.y, 0.5f*(v0.w*v0.w + v1.x*v1.x + v1.y*v1.y));
            shm4[4*t+2] = make_float4(v1.z, v1.w, v2.x, 0.5f*(v1.z*v1.z + v1.w*v1.w + v2.x*v2.x));
            shm4[4*t+3] = make_float4(v2.y, v2.z, v2.w, 0.5f*(v2.y*v2.y + v2.z*v2.z + v2.w*v2.w));
        }
        __syncthreads();
        float qx[4], qy[4], qz[4], best[4];
        int bidx[4];
        int p0 = pg*1024 + t;
        #pragma unroll
        for (int i = 0; i < 4; i++) {
            const float* q = noisy + ((size_t)b*NN + p0 + 256*i) * 3;
            qx[i] = -q[0]; qy[i] = -q[1]; qz[i] = -q[2];
            best[i] = INFINITY; bidx[i] = 0;
        }
        #pragma unroll 2
        for (int j = 0; j < SLTS; j++) {
            float4 v = shm4[j];
            #pragma unroll
            for (int i = 0; i < 4; i++) {
                float e = fmaf(qx[i], v.x, v.w);
                e = fmaf(qy[i], v.y, e);
                e = fmaf(qz[i], v.z, e);
                if (e < best[i]) { best[i] = e; bidx[i] = j; }
            }
        }
        #pragma unroll
        for (int i = 0; i < 4; i++) {
            int pi = b*NN + p0 + 256*i;
            g_pbest[slice*(BB*NN) + pi] = best[i];
            g_pidx [slice*(BB*NN) + pi] = slice*SLTS + bidx[i];
        }
    } else if (blk < PREP_SPW) {
        // ---------------- splitw role ----------------
        float (*ts)[33] = reinterpret_cast<float(*)[33]>(shm4);
        int sb = blk - PREP_NN;
        int m = sb >> 6, tile = sb & 63;
        const float* src; uint32_t *dh, *dl; int N = 256;
        if (m < 4)      { src = ly_w1 + m*65536;     dh = g_w1h + m*32768; dl = g_w1l + m*32768; }
        else if (m < 8) { src = ly_w2 + (m-4)*65536; dh = g_w2h + (m-4)*32768; dl = g_w2l + (m-4)*32768; }
        else            { src = out_w1;              dh = g_owh; dl = g_owl; N = 128; }
        int tn = (tile & 7) * 32, tk = (tile >> 3) * 32;
        if (tn >= N) return;
        int lx = t & 31, ly = t >> 5;
        #pragma unroll
        for (int i = 0; i < 32; i += 8) ts[ly+i][lx] = src[(tk+ly+i)*N + tn + lx];
        __syncthreads();
        int kk = lx & 15; bool ishi = lx < 16;
        int pos = ((kk & 3) << 2) | (kk >> 2);   // M-perm: transpose within 16
        #pragma unroll
        for (int i = 0; i < 32; i += 8) {
            int nl = ly + i;
            float x0 = ts[2*kk][nl], x1 = ts[2*kk+1][nl];
            __half2 hh = __floats2half2_rn(x0, x1);
            float h0 = __low2float(hh), h1 = __high2float(hh);
            __half2 llv = __floats2half2_rn((x0 - h0)*2048.f, (x1 - h1)*2048.f);
            int idx = (tn + nl)*128 + (tk >> 1) + pos;
            if (ishi) dh[idx] = *reinterpret_cast<uint32_t*>(&hh);
            else      dl[idx] = *reinterpret_cast<uint32_t*>(&llv);
        }
    } else {
        // ---------------- temb role (256 threads) ----------------
        float* sp  = (float*)shm4;
        float* emb = sp;           // 128
        float* h1  = sp + 128;     // 512
        float* h2  = sp + 640;     // 512
        int b = blk - PREP_SPW;
        if (t < 64) {
            float fr = expf((float)t * (-logf(10000.0f) / 63.0f));
            float an = (float)timesteps[b] * fr;
            emb[t] = sinf(an); emb[t+64] = cosf(an);
        }
        __syncthreads();
        #pragma unroll
        for (int j = t; j < 512; j += 256) {
            float a = te_b1[j];
            #pragma unroll 4
            for (int k = 0; k < 128; k++) a = fmaf(emb[k], te_w1[k*512+j], a);
            h1[j] = a / (1.0f + expf(-a));
        }
        __syncthreads();
        #pragma unroll
        for (int j = t; j < 512; j += 256) {
            float a = te_b2[j];
            #pragma unroll 4
            for (int k = 0; k < 512; k++) a = fmaf(h1[k], te_w2[k*512+j], a);
            h2[j] = a;
        }
        __syncthreads();
        {
            float a = tp_b[t];
            #pragma unroll 4
            for (int k = 0; k < 512; k++) a = fmaf(h2[k], tp_w[k*256+t], a);
            g_tproj[b*256+t] = a;
        }
    }
}

// ============ fused fp16 weight-pair MLP, B direct from gmem (no k-loop barriers) ============
template<int NT>
__device__ __forceinline__ void gemm_ldg(uint32_t su, int Ao,
                                         const uint32_t* __restrict__ gh,
                                         const uint32_t* __restrict__ gl,
                                         float ch[2][NT][4], float cl[2][NT][4],
                                         int wn, int g, int tt)
{
    const uint32_t* ph[NT];
    const uint32_t* pl[NT];
    #pragma unroll
    for (int nt = 0; nt < NT; nt++) {
        int n = wn*(NT*8) + nt*8 + g;
        ph[nt] = gh + n*128 + tt*4;
        pl[nt] = gl + n*128 + tt*4;
    }
    #pragma unroll
    for (int kc = 0; kc < 8; kc++) {
        uint4 bhv[NT], blv[NT];
        #pragma unroll
        for (int nt = 0; nt < NT; nt++) {
            bhv[nt] = *(const uint4*)(ph[nt] + kc*16);
            blv[nt] = *(const uint4*)(pl[nt] + kc*16);
        }
        uint32_t af[2][2][4];
        #pragma unroll
        for (int mi = 0; mi < 2; mi++) {
            uint32_t ad = su + (uint32_t)((Ao + (mi*16 + g)*144 + kc*16 + tt*4)*4);
            uint32_t q0,q1,q2,q3,p0,p1,p2,p3;
            LD4(q0,q1,q2,q3, ad);
            LD4(p0,p1,p2,p3, ad + 8*144*4);
            af[0][mi][0]=q0; af[0][mi][2]=q1; af[1][mi][0]=q2; af[1][mi][2]=q3;
            af[0][mi][1]=p0; af[0][mi][3]=p1; af[1][mi][1]=p2; af[1][mi][3]=p3;
        }
        #pragma unroll
        for (int ks = 0; ks < 2; ks++)
            #pragma unroll
            for (int mi = 0; mi < 2; mi++)
                #pragma unroll
                for (int nt = 0; nt < NT; nt++) {
                    uint32_t bh[2] = { ks ? bhv[nt].z : bhv[nt].x, ks ? bhv[nt].w : bhv[nt].y };
                    uint32_t bl[2] = { ks ? blv[nt].z : blv[nt].x, ks ? blv[nt].w : blv[nt].y };
                    mmaf16(ch[mi][nt], af[ks][mi], bh);
                    mmaf16(cl[mi][nt], af[ks][mi], bl);
                }
    }
}

__global__ __launch_bounds__(256, 2)
void mlp_f16(const float* __restrict__ noisy, const float* __restrict__ target,
             const float* __restrict__ in_w,  const float* __restrict__ in_b,
             const float* __restrict__ ly_b1, const float* __restrict__ ly_g,
             const float* __restrict__ ly_be, const float* __restrict__ ly_b2,
             const float* __restrict__ out_b1, const float* __restrict__ out_w2,
             const float* __restrict__ out_b2, float* __restrict__ out)
{
    extern __shared__ float sm[];
    uint32_t su = smem_to_u32(sm);
    int t = threadIdx.x, lane = t & 31;
    int wn = t >> 5;                       // warp grid 1(M) x 8(N)
    int g = lane >> 2, tt = lane & 3;
    int b = blockIdx.x >> 8, row0 = (blockIdx.x & 255) << 5;

    float* feat = sm + O_FEAT;

    if (t < 32) {   // fused nn_reduce over 8 slices (ascending => first-min)
        int pi = b*NN + row0 + t;
        float best = g_pbest[pi]; int bi = g_pidx[pi];
        #pragma unroll
        for (int s = 1; s < NSL; s++) {
            float vv = g_pbest[s*(BB*NN) + pi];
            if (vv < best) { best = vv; bi = g_pidx[s*(BB*NN) + pi]; }
        }
        const float* tc = target + ((size_t)b*NN + bi)*3;
        feat[t*6+0] = noisy[(size_t)pi*3+0]; feat[t*6+1] = noisy[(size_t)pi*3+1]; feat[t*6+2] = noisy[(size_t)pi*3+2];
        feat[t*6+3] = tc[0]; feat[t*6+4] = tc[1]; feat[t*6+5] = tc[2];
    }
    __syncthreads();

    // ---- input build in fragment layout -> XH/XL residual planes ----
    {
        const float* tp = g_tproj + b*256;
        float fr[2][2][6];
        #pragma unroll
        for (int mi = 0; mi < 2; mi++)
            #pragma unroll
            for (int h = 0; h < 2; h++) {
                int row = mi*16 + h*8 + g;
                #pragma unroll
                for (int k = 0; k < 6; k++) fr[mi][h][k] = feat[row*6 + k];
            }
        uint32_t wh[2][2][4], wl[2][2][4];
        #pragma unroll
        for (int nt = 0; nt < 4; nt++) {
            int bc = wn*32 + nt*8 + 2*tt;
            float xv[2][2][2];
            #pragma unroll
            for (int half = 0; half < 2; half++) {
                int col = bc + half;
                float base = in_b[col] + tp[col];
                float w[6];
                #pragma unroll
                for (int k = 0; k < 6; k++) w[k] = in_w[k*256 + col];
                #pragma unroll
                for (int mi = 0; mi < 2; mi++)
                    #pragma unroll
                    for (int h = 0; h < 2; h++) {
                        float a = base;
                        #pragma unroll
                        for (int k = 0; k < 6; k++) a = fmaf(fr[mi][h][k], w[k], a);
                        xv[mi][h][half] = a;
                    }
            }
            #pragma unroll
            for (int mi = 0; mi < 2; mi++)
                #pragma unroll
                for (int h = 0; h < 2; h++)
                    splitx2(xv[mi][h][0], xv[mi][h][1], wh[mi][h][nt], wl[mi][h][nt]);
        }
        #pragma unroll
        for (int mi = 0; mi < 2; mi++)
            #pragma unroll
            for (int h = 0; h < 2; h++) {
                int row = mi*16 + h*8 + g;
                uint32_t off = (uint32_t)((row*144 + wn*16 + tt*4)*4);
                ST4(su + (uint32_t)(O_XH*4) + off, wh[mi][h][0], wh[mi][h][1], wh[mi][h][2], wh[mi][h][3]);
                ST4(su + (uint32_t)(O_XL*4) + off, wl[mi][h][0], wl[mi][h][1], wl[mi][h][2], wl[mi][h][3]);
            }
    }
    __syncthreads();   // publish XH/XL

    // ---- 4 residual layers ----
    #pragma unroll 1
    for (int lay = 0; lay < 4; lay++) {
        const float* b1p = ly_b1 + lay*256;
        const float* gap = ly_g  + lay*256;
        const float* bep = ly_be + lay*256;
        const float* b2p = ly_b2 + lay*256;

        // GEMM1: D = x @ W1 (no barriers inside)
        float ch[2][4][4], cl[2][4][4];
        #pragma unroll
        for (int mi = 0; mi < 2; mi++)
            #pragma unroll
            for (int nt = 0; nt < 4; nt++)
                #pragma unroll
                for (int e = 0; e < 4; e++) { ch[mi][nt][e] = 0.f; cl[mi][nt][e] = 0.f; }
        gemm_ldg<4>(su, O_XH, g_w1h + lay*32768, g_w1l + lay*32768, ch, cl, wn, g, tt);

        // epilogue1: combine into ch, LN stats
        float S[2][2] = {{0,0},{0,0}}, Q[2][2] = {{0,0},{0,0}};
        #pragma unroll
        for (int mi = 0; mi < 2; mi++)
            #pragma unroll
            for (int nt = 0; nt < 4; nt++) {
                int bc = wn*32 + nt*8 + 2*tt;
                float b0 = b1p[bc], b1v = b1p[bc + 1];
                float v0 = fmaf(cl[mi][nt][0], INV2048, ch[mi][nt][0]) + b0;
                float v1 = fmaf(cl[mi][nt][1], INV2048, ch[mi][nt][1]) + b1v;
                float v2 = fmaf(cl[mi][nt][2], INV2048, ch[mi][nt][2]) + b0;
                float v3 = fmaf(cl[mi][nt][3], INV2048, ch[mi][nt][3]) + b1v;
                ch[mi][nt][0]=v0; ch[mi][nt][1]=v1; ch[mi][nt][2]=v2; ch[mi][nt][3]=v3;
                S[mi][0] += v0 + v1; Q[mi][0] = fmaf(v0,v0,fmaf(v1,v1,Q[mi][0]));
                S[mi][1] += v2 + v3; Q[mi][1] = fmaf(v2,v2,fmaf(v3,v3,Q[mi][1]));
            }
        #pragma unroll
        for (int mi = 0; mi < 2; mi++)
            #pragma unroll
            for (int h = 0; h < 2; h++) {
                float s = S[mi][h], q = Q[mi][h];
                s += __shfl_xor_sync(~0u, s, 1); s += __shfl_xor_sync(~0u, s, 2);
                q += __shfl_xor_sync(~0u, q, 1); q += __shfl_xor_sync(~0u, q, 2);
                if (tt == 0) {
                    int row = mi*16 + h*8 + g;
                    sm[O_SRS + row*8 + wn] = s;
                    sm[O_SRQ + row*8 + wn] = q;
                }
            }
        __syncthreads();
        if (t < 32) {
            float s = 0.f, q = 0.f;
            #pragma unroll
            for (int i = 0; i < 8; i++) { s += sm[O_SRS + t*8 + i]; q += sm[O_SRQ + t*8 + i]; }
            float mu = s * (1.f/256.f);
            sm[O_RS + t] = rsqrtf(fmaf(-mu, mu, q * (1.f/256.f)) + 1e-5f);
            sm[O_MU + t] = mu;
        }
        __syncthreads();
        // LN + SiLU -> h plane
        #pragma unroll
        for (int mi = 0; mi < 2; mi++)
            #pragma unroll
            for (int h = 0; h < 2; h++) {
                int row = mi*16 + h*8 + g;
                float mu = sm[O_MU + row], rs = sm[O_RS + row];
                uint32_t w4[4];
                #pragma unroll
                for (int nt = 0; nt < 4; nt++) {
                    int bc = wn*32 + nt*8 + 2*tt;
                    float h0 = silu(fmaf((ch[mi][nt][2*h]   - mu)*rs, gap[bc],   bep[bc]));
                    float h1 = silu(fmaf((ch[mi][nt][2*h+1] - mu)*rs, gap[bc+1], bep[bc+1]));
                    w4[nt] = packh2(h0, h1);
                }
                ST4(su + (uint32_t)((O_HH + row*144 + wn*16 + tt*4)*4), w4[0], w4[1], w4[2], w4[3]);
            }
        __syncthreads();   // publish h plane

        // GEMM2: D = h @ W2
        #pragma unroll
        for (int mi = 0; mi < 2; mi++)
            #pragma unroll
            for (int nt = 0; nt < 4; nt++)
                #pragma unroll
                for (int e = 0; e < 4; e++) { ch[mi][nt][e] = 0.f; cl[mi][nt][e] = 0.f; }
        gemm_ldg<4>(su, O_HH, g_w2h + lay*32768, g_w2l + lay*32768, ch, cl, wn, g, tt);

        // epilogue2: x = x_old(XH/XL planes) + D + b2; refresh planes
        #pragma unroll
        for (int mi = 0; mi < 2; mi++)
            #pragma unroll
            for (int h = 0; h < 2; h++) {
                int row = mi*16 + h*8 + g;
                uint32_t off = (uint32_t)((row*144 + wn*16 + tt*4)*4);
                uint32_t oh0,oh1,oh2,oh3, ol0,ol1,ol2,ol3;
                LD4(oh0,oh1,oh2,oh3, su + (uint32_t)(O_XH*4) + off);
                LD4(ol0,ol1,ol2,ol3, su + (uint32_t)(O_XL*4) + off);
                uint32_t ohs[4] = {oh0,oh1,oh2,oh3};
                uint32_t ols[4] = {ol0,ol1,ol2,ol3};
                uint32_t nh[4], nl[4];
                #pragma unroll
                for (int nt = 0; nt < 4; nt++) {
                    int bc = wn*32 + nt*8 + 2*tt;
                    float2 xo = __half22float2(*reinterpret_cast<__half2*>(&ohs[nt]));
                    float2 xl = __half22float2(*reinterpret_cast<__half2*>(&ols[nt]));
                    float x0 = fmaf(xl.x, INV2048, xo.x) + fmaf(cl[mi][nt][2*h],   INV2048, ch[mi][nt][2*h])   + b2p[bc];
                    float x1 = fmaf(xl.y, INV2048, xo.y) + fmaf(cl[mi][nt][2*h+1], INV2048, ch[mi][nt][2*h+1]) + b2p[bc + 1];
                    splitx2(x0, x1, nh[nt], nl[nt]);
                }
                ST4(su + (uint32_t)(O_XH*4) + off, nh[0], nh[1], nh[2], nh[3]);
                ST4(su + (uint32_t)(O_XL*4) + off, nl[0], nl[1], nl[2], nl[3]);
            }
        __syncthreads();   // publish refreshed x planes
    }

    // ---- head GEMM: D = x @ out_w1 (N=128) ----
    {
        float ch[2][2][4], cl[2][2][4];
        #pragma unroll
        for (int mi = 0; mi < 2; mi++)
            #pragma unroll
            for (int nt = 0; nt < 2; nt++)
                #pragma unroll
                for (int e = 0; e < 4; e++) { ch[mi][nt][e] = 0.f; cl[mi][nt][e] = 0.f; }
        gemm_ldg<2>(su, O_XH, g_owh, g_owl, ch, cl, wn, g, tt);

        __syncthreads();   // XH reads done before HH region reused as fp32 y1
        float* y1f = sm + O_HH;
        #pragma unroll
        for (int mi = 0; mi < 2; mi++)
            #pragma unroll
            for (int h = 0; h < 2; h++) {
                int row = mi*16 + h*8 + g;
                #pragma unroll
                for (int nt = 0; nt < 2; nt++) {
                    int bc = wn*16 + nt*8 + 2*tt;
                    float v0 = fmaf(cl[mi][nt][2*h],   INV2048, ch[mi][nt][2*h])   + out_b1[bc];
                    float v1 = fmaf(cl[mi][nt][2*h+1], INV2048, ch[mi][nt][2*h+1]) + out_b1[bc+1];
                    y1f[row*132 + bc]     = silu(v0);
                    y1f[row*132 + bc + 1] = silu(v1);
                }
            }
    }
    __syncthreads();

    // ---- final: score = y1 @ out_w2 + out_b2 (128 -> 3, fp32) ----
    if (t < 96) {
        int rr = t / 3, p = t - rr*3;
        float a = out_b2[p];
        const float* y = sm + O_HH + rr*132;
        #pragma unroll 8
        for (int k = 0; k < 128; k++) a = fmaf(y[k], out_w2[k*3 + p], a);
        out[(size_t)((b*NN + row0 + rr)*3 + p)] = a;
    }
}

// =====================================================================
extern "C" void kernel_launch(void* const* d_in, const int* in_sizes, int n_in,
                              void* d_out, int out_size)
{
    const float* noisy  = (const float*)d_in[0];
    const float* target = (const float*)d_in[1];
    const int*   tsteps = (const int*)  d_in[2];
    const float* te_w1  = (const float*)d_in[3];
    const float* te_b1  = (const float*)d_in[4];
    const float* te_w2  = (const float*)d_in[5];
    const float* te_b2  = (const float*)d_in[6];
    const float* tp_w   = (const float*)d_in[7];
    const float* tp_b   = (const float*)d_in[8];
    const float* in_w   = (const float*)d_in[9];
    const float* in_b   = (const float*)d_in[10];
    const float* ly_w1  = (const float*)d_in[11];
    const float* ly_b1  = (const float*)d_in[12];
    const float* ly_g   = (const float*)d_in[13];
    const float* ly_be  = (const float*)d_in[14];
    const float* ly_w2  = (const float*)d_in[15];
    const float* ly_b2  = (const float*)d_in[16];
    const float* out_w1 = (const float*)d_in[17];
    const float* out_b1 = (const float*)d_in[18];
    const float* out_w2 = (const float*)d_in[19];
    const float* out_b2 = (const float*)d_in[20];
    float* out = (float*)d_out;

    cudaFuncSetAttribute(mlp_f16, cudaFuncAttributeMaxDynamicSharedMemorySize, SMEM_BYTES);

    prep_kernel<<<PREP_TOTAL, 256>>>(noisy, target, tsteps,
                                     te_w1, te_b1, te_w2, te_b2, tp_w, tp_b,
                                     ly_w1, ly_w2, out_w1);
    mlp_f16<<<1024, 256, SMEM_BYTES>>>(noisy, target, in_w, in_b,
                                       ly_b1, ly_g, ly_be, ly_b2,
                                       out_b1, out_w2, out_b2, out);
}